// round 12
// baseline (speedup 1.0000x reference)
#include <cuda_runtime.h>
#include <stdint.h>
#include <stddef.h>

// ---------------------------------------------------------------------------
// JAX PRNG: partitionable threefry (validated: rel_err 1.8e-7)
// ---------------------------------------------------------------------------

#define NROWS_MAX 100000
#define NEDGE_MAX 1200000

struct U2 { uint32_t x, y; };
struct __align__(8) Edge { int col; float val; };

// ------------------------------ threefry2x32 -------------------------------
static __host__ __device__ __forceinline__ uint32_t rotl32(uint32_t x, uint32_t r) {
#ifdef __CUDA_ARCH__
    return __funnelshift_l(x, x, r);
#else
    return (x << r) | (x >> (32u - r));
#endif
}

static __host__ __device__ __forceinline__ U2 threefry2x32(uint32_t k0, uint32_t k1,
                                                           uint32_t x0, uint32_t x1) {
    uint32_t k2 = k0 ^ k1 ^ 0x1BD11BDAu;
    x0 += k0; x1 += k1;
#define TF_R(r) { x0 += x1; x1 = rotl32(x1, r); x1 ^= x0; }
    TF_R(13) TF_R(15) TF_R(26) TF_R(6)   x0 += k1; x1 += k2 + 1u;
    TF_R(17) TF_R(29) TF_R(16) TF_R(24)  x0 += k2; x1 += k0 + 2u;
    TF_R(13) TF_R(15) TF_R(26) TF_R(6)   x0 += k0; x1 += k1 + 3u;
    TF_R(17) TF_R(29) TF_R(16) TF_R(24)  x0 += k1; x1 += k2 + 4u;
    TF_R(13) TF_R(15) TF_R(26) TF_R(6)   x0 += k2; x1 += k0 + 5u;
#undef TF_R
    U2 r; r.x = x0; r.y = x1; return r;
}

// keep (u < 0.9): exact integer form of  bitcast(0x3f800000|bits>>9)-1 < 0.9f
static __device__ __forceinline__ bool keep_90(uint32_t k0, uint32_t k1, uint32_t idx) {
    U2 o = threefry2x32(k0, k1, 0u, idx);
    return (((o.x ^ o.y) >> 9)) < 0x00733333u;
}

// ------------------------------ device scratch -----------------------------
// INVARIANT: g_cnt is all-zero at the start of every kernel_launch call.
// (Zero-initialized at module load; k_scan3 re-zeroes it after consuming it.)
__device__ int      g_cnt[NROWS_MAX];
__device__ int      g_rowptr[NROWS_MAX];
__device__ int      g_rowend[NROWS_MAX];
__device__ int      g_cursor[NROWS_MAX];
__device__ int      g_blk[128];
__device__ uint32_t g_keep[(NEDGE_MAX + 31) / 32];
__device__ int4     g_tmp[NEDGE_MAX];        // {eid, col, val(bits), pad}
__device__ Edge     g_edges[NEDGE_MAX];
__device__ float    g_egoA[(size_t)NROWS_MAX * 64];
__device__ float    g_egoB[(size_t)NROWS_MAX * 64];

// ------------------------------ CSR build ----------------------------------
__global__ void k_hist(const int* __restrict__ rows, int E,
                       uint32_t k0, uint32_t k1) {
    int e = blockIdx.x * blockDim.x + threadIdx.x;
    bool keep = (e < E) && keep_90(k0, k1, (uint32_t)e);
    uint32_t m = __ballot_sync(0xffffffffu, keep);
    if ((e & 31) == 0 && e < E) g_keep[e >> 5] = m;
    if (keep) atomicAdd(&g_cnt[rows[e]], 1);
}

// block-level exclusive scan (coalesced), block totals to g_blk
__global__ void __launch_bounds__(1024) k_scan1(int n) {
    __shared__ int warpsum[32];
    int i = blockIdx.x * 1024 + threadIdx.x;
    int lane = threadIdx.x & 31, wid = threadIdx.x >> 5;
    int c = (i < n) ? g_cnt[i] : 0;

    int v = c;
    #pragma unroll
    for (int o = 1; o < 32; o <<= 1) {
        int u = __shfl_up_sync(0xffffffffu, v, o);
        if (lane >= o) v += u;
    }
    if (lane == 31) warpsum[wid] = v;
    __syncthreads();
    if (wid == 0) {
        int w = warpsum[lane];
        #pragma unroll
        for (int o = 1; o < 32; o <<= 1) {
            int u = __shfl_up_sync(0xffffffffu, w, o);
            if (lane >= o) w += u;
        }
        warpsum[lane] = w;
    }
    __syncthreads();

    int excl = (v - c) + (wid > 0 ? warpsum[wid - 1] : 0);
    if (i < n) g_rowptr[i] = excl;
    if (threadIdx.x == 0) g_blk[blockIdx.x] = warpsum[31];
}

// apply cross-block offsets, write cursor/rowend, RE-ZERO g_cnt.
__global__ void __launch_bounds__(1024) k_scan3(int n, int nb) {
    __shared__ int s_off;
    if (threadIdx.x < 32) {
        int lane = threadIdx.x;
        int acc = 0;
        for (int b = lane; b < nb; b += 32)
            if (b < (int)blockIdx.x) acc += g_blk[b];
        #pragma unroll
        for (int o = 16; o > 0; o >>= 1)
            acc += __shfl_down_sync(0xffffffffu, acc, o);
        if (lane == 0) s_off = acc;
    }
    __syncthreads();
    int i = blockIdx.x * 1024 + threadIdx.x;
    if (i >= n) return;
    int v = g_rowptr[i] + s_off;
    int c = g_cnt[i];
    g_rowptr[i] = v;
    g_cursor[i] = v;
    g_rowend[i] = v + c;
    g_cnt[i]    = 0;
}

// scatter full edge payload; 4 edges per thread => 4 independent
// ATOMG->STG chains in flight. GUARD: t must be < stride, otherwise the
// padding threads would duplicate edges of the q=1 range (R11 bug).
__global__ void k_scatter(const int* __restrict__ rows,
                          const int* __restrict__ cols,
                          const float* __restrict__ vals,
                          int E, int stride) {
    int t = blockIdx.x * blockDim.x + threadIdx.x;
    if (t >= stride) return;
    #pragma unroll
    for (int q = 0; q < 4; q++) {
        int e = t + q * stride;
        if (e < E && ((g_keep[e >> 5] >> (e & 31)) & 1u)) {
            int p = atomicAdd(&g_cursor[rows[e]], 1);
            int4 tt;
            tt.x = e;
            tt.y = cols[e];
            tt.z = __float_as_int(vals[e] * (1.0f / 0.9f));
            tt.w = 0;
            g_tmp[p] = tt;
        }
    }
}

// warp-per-row: bitonic sort (by eid, ascending -> deterministic JAX order),
// coalesced 8B writes of the final Edge list.
__global__ void k_sortfill(int n) {
    int gw = (blockIdx.x * blockDim.x + threadIdx.x) >> 5;  // global warp = row
    if (gw >= n) return;
    int lane = threadIdx.x & 31;
    int s = g_rowptr[gw], end = g_rowend[gw];
    int deg = end - s;

    if (deg <= 32) {
        int eid = 0x7fffffff, col = 0; float val = 0.0f;
        if (lane < deg) {
            int4 t = g_tmp[s + lane];
            eid = t.x; col = t.y; val = __int_as_float(t.z);
        }
        #pragma unroll
        for (int k = 2; k <= 32; k <<= 1) {
            #pragma unroll
            for (int j = k >> 1; j > 0; j >>= 1) {
                int   peid = __shfl_xor_sync(0xffffffffu, eid, j);
                int   pcol = __shfl_xor_sync(0xffffffffu, col, j);
                float pval = __shfl_xor_sync(0xffffffffu, val, j);
                bool up     = ((lane & k) == 0);
                bool lower  = ((lane & j) == 0);
                bool takeSm = (lower == up);
                bool doSwap = takeSm ? (peid < eid) : (peid > eid);
                if (doSwap) { eid = peid; col = pcol; val = pval; }
            }
        }
        if (lane < deg) {
            Edge ed; ed.col = col; ed.val = val;
            g_edges[s + lane] = ed;
        }
    } else if (lane == 0) {   // rare fallback: serial insertion sort in gmem
        for (int i = s + 1; i < end; i++) {
            int4 key = g_tmp[i]; int j = i - 1;
            while (j >= s && g_tmp[j].x > key.x) { g_tmp[j + 1] = g_tmp[j]; j--; }
            g_tmp[j + 1] = key;
        }
        for (int i = s; i < end; i++) {
            int4 t = g_tmp[i];
            Edge ed; ed.col = t.y; ed.val = __int_as_float(t.z);
            g_edges[i] = ed;
        }
    }
}

// ------------------------------ fused layer kernel -------------------------
__device__ __forceinline__ void fma4(float4& a, float v, const float4& x) {
    a.x = fmaf(v, x.x, a.x); a.y = fmaf(v, x.y, a.y);
    a.z = fmaf(v, x.z, a.z); a.w = fmaf(v, x.w, a.w);
}

#define LB_THREADS 256
#define LB_ROWS    64   // rows per block; 4 threads per row

// Warp-local pipeline: warp w owns local rows [8w, 8w+8). One block sync
// (after Ws/bs load), then SpMM -> __syncwarp -> GEMM -> epilogue, all
// warp-independent (no block-max-degree tail).
__global__ void __launch_bounds__(LB_THREADS, 5)
k_layer(int srcSel,                       // 0 = emb param, 1 = egoA, 2 = egoB
        const float4* __restrict__ embIn,
        int dstSel,                       // 1 = egoA, 2 = egoB
        const float* __restrict__ W, const float* __restrict__ b,
        float4* __restrict__ out4,        // out as float4, row stride 64
        int layer,
        uint32_t k0, uint32_t k1,
        int copyEmb, int n)
{
    __shared__ __align__(16) float4 Ws[64 * 16];
    __shared__ __align__(16) float  side[LB_ROWS][68];  // padded (17 float4)
    __shared__ __align__(16) float  bs[64];

    const float4* ego = (srcSel == 0) ? embIn
                       : (srcSel == 1) ? (const float4*)g_egoA : (const float4*)g_egoB;
    float4* egoOut = (dstSel == 1) ? (float4*)g_egoA : (float4*)g_egoB;

    int tid = threadIdx.x;

    const float4* W4 = (const float4*)W;
    for (int i = tid; i < 1024; i += LB_THREADS) Ws[i] = W4[i];
    if (tid < 16) ((float4*)bs)[tid] = ((const float4*)b)[tid];
    __syncthreads();   // the ONLY block-wide sync (Ws/bs visibility)

    int lane = tid & 31;

    // ---- epilogue mapping: lane -> (row lrE, 16 cols starting at cE*16) ----
    int lrE = (tid >> 5) * 8 + (lane >> 2);           // local row 0..63
    int cE  = lane & 3;                               // col group 0..3
    int rowE = blockIdx.x * LB_ROWS + lrE;

    // hoisted dropout mask (ALU overlaps the SpMM gather latency)
    uint32_t mbase = (uint32_t)rowE * 64u + (uint32_t)cE * 16u;
    uint32_t dmask = 0;
    #pragma unroll
    for (int j = 0; j < 16; j++)
        if (keep_90(k0, k1, mbase + (uint32_t)j)) dmask |= 1u << j;

    // -------- SpMM phase: 4 threads per row, each owns 4 float4 slots ------
    int lr = tid >> 2;
    int l4 = tid & 3;
    int r  = blockIdx.x * LB_ROWS + lr;

    float4 a0 = {0,0,0,0}, a1 = a0, a2 = a0, a3 = a0;
    if (r < n) {
        int e   = g_rowptr[r];
        int end = g_rowend[r];
        for (; e + 1 < end; e += 2) {
            Edge e0 = g_edges[e];
            Edge e1 = g_edges[e + 1];
            const float4* p0 = ego + ((size_t)e0.col << 4) + l4;
            const float4* p1 = ego + ((size_t)e1.col << 4) + l4;
            float4 x00 = __ldg(p0),     x01 = __ldg(p0 + 4),
                   x02 = __ldg(p0 + 8), x03 = __ldg(p0 + 12);
            float4 x10 = __ldg(p1),     x11 = __ldg(p1 + 4),
                   x12 = __ldg(p1 + 8), x13 = __ldg(p1 + 12);
            fma4(a0, e0.val, x00); fma4(a1, e0.val, x01);
            fma4(a2, e0.val, x02); fma4(a3, e0.val, x03);
            fma4(a0, e1.val, x10); fma4(a1, e1.val, x11);
            fma4(a2, e1.val, x12); fma4(a3, e1.val, x13);
        }
        if (e < end) {
            Edge e0 = g_edges[e];
            const float4* p0 = ego + ((size_t)e0.col << 4) + l4;
            fma4(a0, e0.val, __ldg(p0));     fma4(a1, e0.val, __ldg(p0 + 4));
            fma4(a2, e0.val, __ldg(p0 + 8)); fma4(a3, e0.val, __ldg(p0 + 12));
        }
    }
    {
        float4* sp = (float4*)(&side[lr][0]);
        sp[l4] = a0; sp[l4 + 4] = a1; sp[l4 + 8] = a2; sp[l4 + 12] = a3;
    }
    __syncwarp();   // warp-local: this warp wrote rows [8w,8w+8) itself

    // -------- GEMM phase (warp-local): lane -> row lrE, cols cE*16..+15 -----
    float4 h[4];
    #pragma unroll
    for (int j = 0; j < 4; j++) h[j] = ((const float4*)bs)[cE * 4 + j];

    const float* srow = &side[lrE][0];
    #pragma unroll 16
    for (int k = 0; k < 64; k++) {
        float s = srow[k];
        const float4* wrow = &Ws[k * 16 + cE * 4];
        #pragma unroll
        for (int j = 0; j < 4; j++) {
            float4 w = wrow[j];
            h[j].x = fmaf(s, w.x, h[j].x);
            h[j].y = fmaf(s, w.y, h[j].y);
            h[j].z = fmaf(s, w.z, h[j].z);
            h[j].w = fmaf(s, w.w, h[j].w);
        }
    }

    // -------- dropout (precomputed) + row-norm (4-lane reduce) + writes -----
    float ss = 0.0f;
    #pragma unroll
    for (int j = 0; j < 4; j++) {
        h[j].x = (dmask >> (j * 4 + 0)) & 1u ? h[j].x * (1.0f / 0.9f) : 0.0f;
        h[j].y = (dmask >> (j * 4 + 1)) & 1u ? h[j].y * (1.0f / 0.9f) : 0.0f;
        h[j].z = (dmask >> (j * 4 + 2)) & 1u ? h[j].z * (1.0f / 0.9f) : 0.0f;
        h[j].w = (dmask >> (j * 4 + 3)) & 1u ? h[j].w * (1.0f / 0.9f) : 0.0f;
        ss += h[j].x * h[j].x + h[j].y * h[j].y
            + h[j].z * h[j].z + h[j].w * h[j].w;
    }
    // lanes 4r..4r+3 share row lrE -> reduce across xor masks 1,2
    ss += __shfl_xor_sync(0xffffffffu, ss, 1);
    ss += __shfl_xor_sync(0xffffffffu, ss, 2);

    float invn = 1.0f / fmaxf(sqrtf(ss), 1e-12f);

    if (rowE < n) {
        #pragma unroll
        for (int j = 0; j < 4; j++) {
            egoOut[(size_t)rowE * 16 + cE * 4 + j] = h[j];
            float4 o;
            o.x = h[j].x * invn; o.y = h[j].y * invn;
            o.z = h[j].z * invn; o.w = h[j].w * invn;
            out4[(size_t)rowE * 64 + (size_t)(layer + 1) * 16 + cE * 4 + j] = o;
            if (copyEmb)
                out4[(size_t)rowE * 64 + cE * 4 + j] =
                    embIn[(size_t)rowE * 16 + cE * 4 + j];
        }
    }
}

// ------------------------------ host entry ---------------------------------
extern "C" void kernel_launch(void* const* d_in, const int* in_sizes, int n_in,
                              void* d_out, int out_size) {
    const int*   rows = (const int*)d_in[0];
    const int*   cols = (const int*)d_in[1];
    const float* vals = (const float*)d_in[2];
    const float* emb  = (const float*)d_in[3];
    const float* W0   = (const float*)d_in[4];
    const float* b0   = (const float*)d_in[5];
    const float* W1   = (const float*)d_in[6];
    const float* b1   = (const float*)d_in[7];
    const float* W2   = (const float*)d_in[8];
    const float* b2   = (const float*)d_in[9];

    int E = in_sizes[0];
    int N = in_sizes[3] / 64;
    if (E > NEDGE_MAX) E = NEDGE_MAX;
    if (N > NROWS_MAX) N = NROWS_MAX;
    float* out = (float*)d_out;

    // subkeys of jax.random.key(42) -> split(.,4): [k_node, k0, k1, k2]
    U2 kn = threefry2x32(0u, 42u, 0u, 0u);
    U2 kA = threefry2x32(0u, 42u, 0u, 1u);
    U2 kB = threefry2x32(0u, 42u, 0u, 2u);
    U2 kC = threefry2x32(0u, 42u, 0u, 3u);

    int tb = 256;
    int nb = (N + 1023) / 1024;
    int quarter = (E + 3) / 4;
    // launches: [0]hist [1]scan1 [2]scan3 [3]scatter <- ncu
    //           [4]sortfill [5]layer0 [6]layer1 [7]layer2
    k_hist    <<<(E + tb - 1) / tb, tb>>>(rows, E, kn.x, kn.y);
    k_scan1   <<<nb, 1024>>>(N);
    k_scan3   <<<nb, 1024>>>(N, nb);
    k_scatter <<<(quarter + tb - 1) / tb, tb>>>(rows, cols, vals, E, quarter);
    k_sortfill<<<(N + 7) / 8, 256>>>(N);   // warp per row

    int gb = (N + LB_ROWS - 1) / LB_ROWS;
    k_layer<<<gb, LB_THREADS>>>(0, (const float4*)emb, 1, W0, b0,
                                (float4*)out, 0, kA.x, kA.y, 1, N);
    k_layer<<<gb, LB_THREADS>>>(1, (const float4*)emb, 2, W1, b1,
                                (float4*)out, 1, kB.x, kB.y, 0, N);
    k_layer<<<gb, LB_THREADS>>>(2, (const float4*)emb, 1, W2, b2,
                                (float4*)out, 2, kC.x, kC.y, 0, N);
}

// round 13
// speedup vs baseline: 1.8901x; 1.8901x over previous
#include <cuda_runtime.h>
#include <stdint.h>
#include <stddef.h>

// ---------------------------------------------------------------------------
// JAX PRNG: partitionable threefry (validated: rel_err 1.8e-7)
// Config: R8 baseline (275.9us) + MLP-4 hist. Layer kernel is UNTOUCHED R8.
// ---------------------------------------------------------------------------

#define NROWS_MAX 100000
#define NEDGE_MAX 1200000

struct U2 { uint32_t x, y; };
struct __align__(8) Edge { int col; float val; };

// ------------------------------ threefry2x32 -------------------------------
static __host__ __device__ __forceinline__ uint32_t rotl32(uint32_t x, uint32_t r) {
#ifdef __CUDA_ARCH__
    return __funnelshift_l(x, x, r);
#else
    return (x << r) | (x >> (32u - r));
#endif
}

static __host__ __device__ __forceinline__ U2 threefry2x32(uint32_t k0, uint32_t k1,
                                                           uint32_t x0, uint32_t x1) {
    uint32_t k2 = k0 ^ k1 ^ 0x1BD11BDAu;
    x0 += k0; x1 += k1;
#define TF_R(r) { x0 += x1; x1 = rotl32(x1, r); x1 ^= x0; }
    TF_R(13) TF_R(15) TF_R(26) TF_R(6)   x0 += k1; x1 += k2 + 1u;
    TF_R(17) TF_R(29) TF_R(16) TF_R(24)  x0 += k2; x1 += k0 + 2u;
    TF_R(13) TF_R(15) TF_R(26) TF_R(6)   x0 += k0; x1 += k1 + 3u;
    TF_R(17) TF_R(29) TF_R(16) TF_R(24)  x0 += k1; x1 += k2 + 4u;
    TF_R(13) TF_R(15) TF_R(26) TF_R(6)   x0 += k2; x1 += k0 + 5u;
#undef TF_R
    U2 r; r.x = x0; r.y = x1; return r;
}

// keep (u < 0.9): exact integer form of  bitcast(0x3f800000|bits>>9)-1 < 0.9f
static __device__ __forceinline__ bool keep_90(uint32_t k0, uint32_t k1, uint32_t idx) {
    U2 o = threefry2x32(k0, k1, 0u, idx);
    return (((o.x ^ o.y) >> 9)) < 0x00733333u;
}

// ------------------------------ device scratch -----------------------------
// INVARIANT: g_cnt is all-zero at the start of every kernel_launch call.
// (Zero-initialized at module load; k_scan3 re-zeroes it after consuming it.)
__device__ int      g_cnt[NROWS_MAX];
__device__ int      g_rowptr[NROWS_MAX];
__device__ int      g_rowend[NROWS_MAX];
__device__ int      g_cursor[NROWS_MAX];
__device__ int      g_blk[128];
__device__ uint32_t g_keep[(NEDGE_MAX + 31) / 32];
__device__ int      g_eid[NEDGE_MAX];
__device__ Edge     g_edges[NEDGE_MAX];
__device__ float    g_egoA[(size_t)NROWS_MAX * 64];
__device__ float    g_egoB[(size_t)NROWS_MAX * 64];

// ------------------------------ CSR build ----------------------------------
// 4 strided edges per thread (4 independent cipher+atomic chains). No early
// return: every lane participates in all 4 ballots. stride is a multiple of
// 32, so e%32 == t%32 and ballot words align with g_keep words exactly as in
// the 1-edge-per-thread version (bit i of word e>>5 == edge e_base+i).
__global__ void k_hist(const int* __restrict__ rows, int E,
                       uint32_t k0, uint32_t k1, int stride) {
    int t = blockIdx.x * blockDim.x + threadIdx.x;
    #pragma unroll
    for (int q = 0; q < 4; q++) {
        int e = t + q * stride;
        bool inb  = (t < stride) && (e < E);
        bool keep = inb && keep_90(k0, k1, (uint32_t)e);
        uint32_t m = __ballot_sync(0xffffffffu, keep);
        if (((e & 31) == 0) && inb) g_keep[e >> 5] = m;
        if (keep) atomicAdd(&g_cnt[rows[e]], 1);
    }
}

// block-level exclusive scan (coalesced), block totals to g_blk
__global__ void __launch_bounds__(1024) k_scan1(int n) {
    __shared__ int warpsum[32];
    int i = blockIdx.x * 1024 + threadIdx.x;
    int lane = threadIdx.x & 31, wid = threadIdx.x >> 5;
    int c = (i < n) ? g_cnt[i] : 0;

    int v = c;
    #pragma unroll
    for (int o = 1; o < 32; o <<= 1) {
        int u = __shfl_up_sync(0xffffffffu, v, o);
        if (lane >= o) v += u;
    }
    if (lane == 31) warpsum[wid] = v;
    __syncthreads();
    if (wid == 0) {
        int w = warpsum[lane];
        #pragma unroll
        for (int o = 1; o < 32; o <<= 1) {
            int u = __shfl_up_sync(0xffffffffu, w, o);
            if (lane >= o) w += u;
        }
        warpsum[lane] = w;
    }
    __syncthreads();

    int excl = (v - c) + (wid > 0 ? warpsum[wid - 1] : 0);
    if (i < n) g_rowptr[i] = excl;
    if (threadIdx.x == 0) g_blk[blockIdx.x] = warpsum[31];
}

// apply cross-block offsets, write cursor/rowend, RE-ZERO g_cnt.
__global__ void __launch_bounds__(1024) k_scan3(int n, int nb) {
    __shared__ int s_off;
    if (threadIdx.x < 32) {
        int lane = threadIdx.x;
        int acc = 0;
        for (int b = lane; b < nb; b += 32)
            if (b < (int)blockIdx.x) acc += g_blk[b];
        #pragma unroll
        for (int o = 16; o > 0; o >>= 1)
            acc += __shfl_down_sync(0xffffffffu, acc, o);
        if (lane == 0) s_off = acc;
    }
    __syncthreads();
    int i = blockIdx.x * 1024 + threadIdx.x;
    if (i >= n) return;
    int v = g_rowptr[i] + s_off;
    int c = g_cnt[i];
    g_rowptr[i] = v;
    g_cursor[i] = v;
    g_rowend[i] = v + c;
    g_cnt[i]    = 0;
}

__global__ void k_scatter(const int* __restrict__ rows, int E) {
    int e = blockIdx.x * blockDim.x + threadIdx.x;
    if (e >= E) return;
    if ((g_keep[e >> 5] >> (e & 31)) & 1u) {
        int p = atomicAdd(&g_cursor[rows[e]], 1);
        g_eid[p] = e;
    }
}

// deterministic ordering: sort each row's edge ids ascending, then materialize
__global__ void k_sortfill(const int* __restrict__ cols,
                           const float* __restrict__ vals, int n) {
    int r = blockIdx.x * blockDim.x + threadIdx.x;
    if (r >= n) return;
    int s = g_rowptr[r], t = g_rowend[r];
    for (int i = s + 1; i < t; i++) {
        int key = g_eid[i];
        int j = i - 1;
        while (j >= s && g_eid[j] > key) { g_eid[j + 1] = g_eid[j]; j--; }
        g_eid[j + 1] = key;
    }
    for (int i = s; i < t; i++) {
        int e = g_eid[i];
        Edge ed; ed.col = cols[e]; ed.val = vals[e] * (1.0f / 0.9f);
        g_edges[i] = ed;
    }
}

// ------------------------------ fused layer kernel -------------------------
__device__ __forceinline__ void fma4(float4& a, float v, const float4& x) {
    a.x = fmaf(v, x.x, a.x); a.y = fmaf(v, x.y, a.y);
    a.z = fmaf(v, x.z, a.z); a.w = fmaf(v, x.w, a.w);
}

#define LB_THREADS 256
#define LB_ROWS    64   // rows per block; 4 threads per row in SpMM phase

__global__ void __launch_bounds__(LB_THREADS, 5)
k_layer(int srcSel,                       // 0 = emb param, 1 = egoA, 2 = egoB
        const float4* __restrict__ embIn,
        int dstSel,                       // 1 = egoA, 2 = egoB
        const float* __restrict__ W, const float* __restrict__ b,
        float4* __restrict__ out4,        // out as float4, row stride 64
        int layer,
        uint32_t k0, uint32_t k1,
        int copyEmb, int n)
{
    __shared__ __align__(16) float4 Ws[64 * 16];
    __shared__ __align__(16) float  side[LB_ROWS][68];  // padded (17 float4)
    __shared__ __align__(16) float  bs[64];

    const float4* ego = (srcSel == 0) ? embIn
                       : (srcSel == 1) ? (const float4*)g_egoA : (const float4*)g_egoB;
    float4* egoOut = (dstSel == 1) ? (float4*)g_egoA : (float4*)g_egoB;

    int tid = threadIdx.x;

    const float4* W4 = (const float4*)W;
    for (int i = tid; i < 1024; i += LB_THREADS) Ws[i] = W4[i];
    if (tid < 16) ((float4*)bs)[tid] = ((const float4*)b)[tid];

    // ---- hoisted dropout mask (ALU work overlaps the SpMM gather latency) --
    int cg = tid & 15;
    int rq = tid >> 4;
    int rbase = blockIdx.x * LB_ROWS + rq * 4;
    uint32_t dmask = 0;
    #pragma unroll
    for (int m = 0; m < 4; m++) {
        uint32_t base = (uint32_t)(rbase + m) * 64u + (uint32_t)cg * 4u;
        #pragma unroll
        for (int j = 0; j < 4; j++)
            if (keep_90(k0, k1, base + (uint32_t)j)) dmask |= 1u << (m * 4 + j);
    }

    // -------- SpMM phase: 4 threads per row, each owns 4 float4 slots ------
    int lr = tid >> 2;
    int l4 = tid & 3;
    int r  = blockIdx.x * LB_ROWS + lr;

    float4 a0 = {0,0,0,0}, a1 = a0, a2 = a0, a3 = a0;
    if (r < n) {
        int e   = g_rowptr[r];
        int end = g_rowend[r];
        for (; e + 1 < end; e += 2) {
            Edge e0 = g_edges[e];
            Edge e1 = g_edges[e + 1];
            const float4* p0 = ego + ((size_t)e0.col << 4) + l4;
            const float4* p1 = ego + ((size_t)e1.col << 4) + l4;
            float4 x00 = __ldg(p0),     x01 = __ldg(p0 + 4),
                   x02 = __ldg(p0 + 8), x03 = __ldg(p0 + 12);
            float4 x10 = __ldg(p1),     x11 = __ldg(p1 + 4),
                   x12 = __ldg(p1 + 8), x13 = __ldg(p1 + 12);
            fma4(a0, e0.val, x00); fma4(a1, e0.val, x01);
            fma4(a2, e0.val, x02); fma4(a3, e0.val, x03);
            fma4(a0, e1.val, x10); fma4(a1, e1.val, x11);
            fma4(a2, e1.val, x12); fma4(a3, e1.val, x13);
        }
        if (e < end) {
            Edge e0 = g_edges[e];
            const float4* p0 = ego + ((size_t)e0.col << 4) + l4;
            fma4(a0, e0.val, __ldg(p0));     fma4(a1, e0.val, __ldg(p0 + 4));
            fma4(a2, e0.val, __ldg(p0 + 8)); fma4(a3, e0.val, __ldg(p0 + 12));
        }
    }
    {
        float4* sp = (float4*)(&side[lr][0]);
        sp[l4] = a0; sp[l4 + 4] = a1; sp[l4 + 8] = a2; sp[l4 + 12] = a3;
    }
    __syncthreads();

    // -------- GEMM phase: thread = 4 cols (cg) x 4 rows (rq) ----------------
    float4 h[4];
    float4 bb = ((const float4*)bs)[cg];
    #pragma unroll
    for (int m = 0; m < 4; m++) h[m] = bb;

    #pragma unroll 16
    for (int k = 0; k < 64; k++) {
        float4 w = Ws[k * 16 + cg];
        #pragma unroll
        for (int m = 0; m < 4; m++) {
            float s = side[rq * 4 + m][k];
            h[m].x = fmaf(s, w.x, h[m].x);
            h[m].y = fmaf(s, w.y, h[m].y);
            h[m].z = fmaf(s, w.z, h[m].z);
            h[m].w = fmaf(s, w.w, h[m].w);
        }
    }

    // -------- dropout (precomputed mask) + ego_next + row-norm + out --------
    #pragma unroll
    for (int m = 0; m < 4; m++) {
        int row = rbase + m;
        float4 hm = h[m];
        hm.x = (dmask >> (m * 4 + 0)) & 1u ? hm.x * (1.0f / 0.9f) : 0.0f;
        hm.y = (dmask >> (m * 4 + 1)) & 1u ? hm.y * (1.0f / 0.9f) : 0.0f;
        hm.z = (dmask >> (m * 4 + 2)) & 1u ? hm.z * (1.0f / 0.9f) : 0.0f;
        hm.w = (dmask >> (m * 4 + 3)) & 1u ? hm.w * (1.0f / 0.9f) : 0.0f;

        float ss = hm.x * hm.x + hm.y * hm.y + hm.z * hm.z + hm.w * hm.w;
        #pragma unroll
        for (int msk = 1; msk <= 8; msk <<= 1)
            ss += __shfl_xor_sync(0xffffffffu, ss, msk);

        float nrm  = sqrtf(ss);
        float invn = 1.0f / fmaxf(nrm, 1e-12f);

        if (row < n) {
            egoOut[(size_t)row * 16 + cg] = hm;
            float4 o;
            o.x = hm.x * invn; o.y = hm.y * invn;
            o.z = hm.z * invn; o.w = hm.w * invn;
            out4[(size_t)row * 64 + (size_t)(layer + 1) * 16 + cg] = o;
            if (copyEmb)
                out4[(size_t)row * 64 + cg] = embIn[(size_t)row * 16 + cg];
        }
    }
}

// ------------------------------ host entry ---------------------------------
extern "C" void kernel_launch(void* const* d_in, const int* in_sizes, int n_in,
                              void* d_out, int out_size) {
    const int*   rows = (const int*)d_in[0];
    const int*   cols = (const int*)d_in[1];
    const float* vals = (const float*)d_in[2];
    const float* emb  = (const float*)d_in[3];
    const float* W0   = (const float*)d_in[4];
    const float* b0   = (const float*)d_in[5];
    const float* W1   = (const float*)d_in[6];
    const float* b1   = (const float*)d_in[7];
    const float* W2   = (const float*)d_in[8];
    const float* b2   = (const float*)d_in[9];

    int E = in_sizes[0];
    int N = in_sizes[3] / 64;
    if (E > NEDGE_MAX) E = NEDGE_MAX;
    if (N > NROWS_MAX) N = NROWS_MAX;
    float* out = (float*)d_out;

    // subkeys of jax.random.key(42) -> split(.,4): [k_node, k0, k1, k2]
    U2 kn = threefry2x32(0u, 42u, 0u, 0u);
    U2 kA = threefry2x32(0u, 42u, 0u, 1u);
    U2 kB = threefry2x32(0u, 42u, 0u, 2u);
    U2 kC = threefry2x32(0u, 42u, 0u, 3u);

    int tb = 256;
    int nb = (N + 1023) / 1024;
    // hist stride: quarter of E, rounded UP to a multiple of 32 so ballot
    // words stay aligned with g_keep words. 4*stride >= E covers all edges;
    // t < stride gives a unique (t,q) decomposition (no duplicates).
    int hstride = (((E + 3) / 4) + 31) & ~31;
    // launches: [0]hist [1]scan1 [2]scan3 [3]scatter <- ncu
    //           [4]sortfill [5]layer0 [6]layer1 [7]layer2
    k_hist    <<<(hstride + tb - 1) / tb, tb>>>(rows, E, kn.x, kn.y, hstride);
    k_scan1   <<<nb, 1024>>>(N);
    k_scan3   <<<nb, 1024>>>(N, nb);
    k_scatter <<<(E + tb - 1) / tb, tb>>>(rows, E);
    k_sortfill<<<(N + tb - 1) / tb, tb>>>(cols, vals, N);

    int gb = (N + LB_ROWS - 1) / LB_ROWS;
    k_layer<<<gb, LB_THREADS>>>(0, (const float4*)emb, 1, W0, b0,
                                (float4*)out, 0, kA.x, kA.y, 1, N);
    k_layer<<<gb, LB_THREADS>>>(1, (const float4*)emb, 2, W1, b1,
                                (float4*)out, 1, kB.x, kB.y, 0, N);
    k_layer<<<gb, LB_THREADS>>>(2, (const float4*)emb, 1, W2, b2,
                                (float4*)out, 2, kC.x, kC.y, 0, N);
}

// round 14
// speedup vs baseline: 1.9327x; 1.0226x over previous
#include <cuda_runtime.h>
#include <stdint.h>
#include <stddef.h>

// ---------------------------------------------------------------------------
// JAX PRNG: partitionable threefry (validated: rel_err 1.8e-7)
// Config: R13 prologue + redesigned layer (8 thr/row SpMM, 32 rows/block,
//         small reg working set -> 6 blocks/SM without spills).
// ---------------------------------------------------------------------------

#define NROWS_MAX 100000
#define NEDGE_MAX 1200000

struct U2 { uint32_t x, y; };
struct __align__(8) Edge { int col; float val; };

// ------------------------------ threefry2x32 -------------------------------
static __host__ __device__ __forceinline__ uint32_t rotl32(uint32_t x, uint32_t r) {
#ifdef __CUDA_ARCH__
    return __funnelshift_l(x, x, r);
#else
    return (x << r) | (x >> (32u - r));
#endif
}

static __host__ __device__ __forceinline__ U2 threefry2x32(uint32_t k0, uint32_t k1,
                                                           uint32_t x0, uint32_t x1) {
    uint32_t k2 = k0 ^ k1 ^ 0x1BD11BDAu;
    x0 += k0; x1 += k1;
#define TF_R(r) { x0 += x1; x1 = rotl32(x1, r); x1 ^= x0; }
    TF_R(13) TF_R(15) TF_R(26) TF_R(6)   x0 += k1; x1 += k2 + 1u;
    TF_R(17) TF_R(29) TF_R(16) TF_R(24)  x0 += k2; x1 += k0 + 2u;
    TF_R(13) TF_R(15) TF_R(26) TF_R(6)   x0 += k0; x1 += k1 + 3u;
    TF_R(17) TF_R(29) TF_R(16) TF_R(24)  x0 += k1; x1 += k2 + 4u;
    TF_R(13) TF_R(15) TF_R(26) TF_R(6)   x0 += k2; x1 += k0 + 5u;
#undef TF_R
    U2 r; r.x = x0; r.y = x1; return r;
}

// keep (u < 0.9): exact integer form of  bitcast(0x3f800000|bits>>9)-1 < 0.9f
static __device__ __forceinline__ bool keep_90(uint32_t k0, uint32_t k1, uint32_t idx) {
    U2 o = threefry2x32(k0, k1, 0u, idx);
    return (((o.x ^ o.y) >> 9)) < 0x00733333u;
}

// ------------------------------ device scratch -----------------------------
// INVARIANT: g_cnt is all-zero at the start of every kernel_launch call.
// (Zero-initialized at module load; k_scan3 re-zeroes it after consuming it.)
__device__ int      g_cnt[NROWS_MAX];
__device__ int      g_rowptr[NROWS_MAX];
__device__ int      g_rowend[NROWS_MAX];
__device__ int      g_cursor[NROWS_MAX];
__device__ int      g_blk[128];
__device__ uint32_t g_keep[(NEDGE_MAX + 31) / 32];
__device__ int      g_eid[NEDGE_MAX];
__device__ Edge     g_edges[NEDGE_MAX];
__device__ float    g_egoA[(size_t)NROWS_MAX * 64];
__device__ float    g_egoB[(size_t)NROWS_MAX * 64];

// ------------------------------ CSR build ----------------------------------
__global__ void k_hist(const int* __restrict__ rows, int E,
                       uint32_t k0, uint32_t k1, int stride) {
    int t = blockIdx.x * blockDim.x + threadIdx.x;
    #pragma unroll
    for (int q = 0; q < 4; q++) {
        int e = t + q * stride;
        bool inb  = (t < stride) && (e < E);
        bool keep = inb && keep_90(k0, k1, (uint32_t)e);
        uint32_t m = __ballot_sync(0xffffffffu, keep);
        if (((e & 31) == 0) && inb) g_keep[e >> 5] = m;
        if (keep) atomicAdd(&g_cnt[rows[e]], 1);
    }
}

// block-level exclusive scan (coalesced), block totals to g_blk
__global__ void __launch_bounds__(1024) k_scan1(int n) {
    __shared__ int warpsum[32];
    int i = blockIdx.x * 1024 + threadIdx.x;
    int lane = threadIdx.x & 31, wid = threadIdx.x >> 5;
    int c = (i < n) ? g_cnt[i] : 0;

    int v = c;
    #pragma unroll
    for (int o = 1; o < 32; o <<= 1) {
        int u = __shfl_up_sync(0xffffffffu, v, o);
        if (lane >= o) v += u;
    }
    if (lane == 31) warpsum[wid] = v;
    __syncthreads();
    if (wid == 0) {
        int w = warpsum[lane];
        #pragma unroll
        for (int o = 1; o < 32; o <<= 1) {
            int u = __shfl_up_sync(0xffffffffu, w, o);
            if (lane >= o) w += u;
        }
        warpsum[lane] = w;
    }
    __syncthreads();

    int excl = (v - c) + (wid > 0 ? warpsum[wid - 1] : 0);
    if (i < n) g_rowptr[i] = excl;
    if (threadIdx.x == 0) g_blk[blockIdx.x] = warpsum[31];
}

// apply cross-block offsets, write cursor/rowend, RE-ZERO g_cnt.
__global__ void __launch_bounds__(1024) k_scan3(int n, int nb) {
    __shared__ int s_off;
    if (threadIdx.x < 32) {
        int lane = threadIdx.x;
        int acc = 0;
        for (int b = lane; b < nb; b += 32)
            if (b < (int)blockIdx.x) acc += g_blk[b];
        #pragma unroll
        for (int o = 16; o > 0; o >>= 1)
            acc += __shfl_down_sync(0xffffffffu, acc, o);
        if (lane == 0) s_off = acc;
    }
    __syncthreads();
    int i = blockIdx.x * 1024 + threadIdx.x;
    if (i >= n) return;
    int v = g_rowptr[i] + s_off;
    int c = g_cnt[i];
    g_rowptr[i] = v;
    g_cursor[i] = v;
    g_rowend[i] = v + c;
    g_cnt[i]    = 0;
}

__global__ void k_scatter(const int* __restrict__ rows, int E) {
    int e = blockIdx.x * blockDim.x + threadIdx.x;
    if (e >= E) return;
    if ((g_keep[e >> 5] >> (e & 31)) & 1u) {
        int p = atomicAdd(&g_cursor[rows[e]], 1);
        g_eid[p] = e;
    }
}

// deterministic ordering: sort each row's edge ids ascending, then materialize
__global__ void k_sortfill(const int* __restrict__ cols,
                           const float* __restrict__ vals, int n) {
    int r = blockIdx.x * blockDim.x + threadIdx.x;
    if (r >= n) return;
    int s = g_rowptr[r], t = g_rowend[r];
    for (int i = s + 1; i < t; i++) {
        int key = g_eid[i];
        int j = i - 1;
        while (j >= s && g_eid[j] > key) { g_eid[j + 1] = g_eid[j]; j--; }
        g_eid[j + 1] = key;
    }
    for (int i = s; i < t; i++) {
        int e = g_eid[i];
        Edge ed; ed.col = cols[e]; ed.val = vals[e] * (1.0f / 0.9f);
        g_edges[i] = ed;
    }
}

// ------------------------------ fused layer kernel -------------------------
__device__ __forceinline__ void fma4(float4& a, float v, const float4& x) {
    a.x = fmaf(v, x.x, a.x); a.y = fmaf(v, x.y, a.y);
    a.z = fmaf(v, x.z, a.z); a.w = fmaf(v, x.w, a.w);
}

#define LB_THREADS 256
#define LB_ROWS    32   // rows per block; 8 threads per row in SpMM phase

// SpMM: 8 threads/row, each owns float4 slots {sub, sub+8} (cols sub*4..+3
// and sub*4+32..+35). Per edge: 2 fully-contiguous 128B warp segments
// (2 L1 wavefronts/edge, half of the old layout). Small reg working set
// (8 acc + 16 temps) -> fits 42-reg cap for 6 blocks/SM.
__global__ void __launch_bounds__(LB_THREADS, 6)
k_layer(int srcSel,                       // 0 = emb param, 1 = egoA, 2 = egoB
        const float4* __restrict__ embIn,
        int dstSel,                       // 1 = egoA, 2 = egoB
        const float* __restrict__ W, const float* __restrict__ b,
        float4* __restrict__ out4,        // out as float4, row stride 64
        int layer,
        uint32_t k0, uint32_t k1,
        int copyEmb, int n)
{
    __shared__ __align__(16) float4 Ws[64 * 16];
    __shared__ __align__(16) float  side[LB_ROWS][68];  // padded (17 float4)
    __shared__ __align__(16) float  bs[64];

    const float4* ego = (srcSel == 0) ? embIn
                       : (srcSel == 1) ? (const float4*)g_egoA : (const float4*)g_egoB;
    float4* egoOut = (dstSel == 1) ? (float4*)g_egoA : (float4*)g_egoB;

    int tid = threadIdx.x;

    const float4* W4 = (const float4*)W;
    for (int i = tid; i < 1024; i += LB_THREADS) Ws[i] = W4[i];
    if (tid < 16) ((float4*)bs)[tid] = ((const float4*)b)[tid];

    // ---- hoisted dropout mask: 2 rows x 4 cols = 8 ciphers/thread ----------
    int cg = tid & 15;          // col group: cols cg*4..cg*4+3
    int rr = tid >> 4;          // row pair index 0..15
    int row0 = blockIdx.x * LB_ROWS + rr * 2;
    uint32_t dmask = 0;
    #pragma unroll
    for (int m = 0; m < 2; m++) {
        uint32_t base = (uint32_t)(row0 + m) * 64u + (uint32_t)cg * 4u;
        #pragma unroll
        for (int j = 0; j < 4; j++)
            if (keep_90(k0, k1, base + (uint32_t)j)) dmask |= 1u << (m * 4 + j);
    }

    // -------- SpMM phase: 8 threads per row, 2 float4 slots each -----------
    int lr  = tid >> 3;         // local row 0..31
    int sub = tid & 7;          // slot 0..7
    int r   = blockIdx.x * LB_ROWS + lr;

    float4 acc0 = {0,0,0,0}, acc1 = acc0;
    if (r < n) {
        int e   = g_rowptr[r];
        int end = g_rowend[r];
        for (; e + 1 < end; e += 2) {
            Edge e0 = g_edges[e];
            Edge e1 = g_edges[e + 1];
            const float4* p0 = ego + ((size_t)e0.col << 4) + sub;
            const float4* p1 = ego + ((size_t)e1.col << 4) + sub;
            float4 x00 = __ldg(p0), x01 = __ldg(p0 + 8);
            float4 x10 = __ldg(p1), x11 = __ldg(p1 + 8);
            fma4(acc0, e0.val, x00); fma4(acc1, e0.val, x01);
            fma4(acc0, e1.val, x10); fma4(acc1, e1.val, x11);
        }
        if (e < end) {
            Edge e0 = g_edges[e];
            const float4* p0 = ego + ((size_t)e0.col << 4) + sub;
            fma4(acc0, e0.val, __ldg(p0));
            fma4(acc1, e0.val, __ldg(p0 + 8));
        }
    }
    {
        float4* sp = (float4*)(&side[lr][0]);
        sp[sub] = acc0; sp[sub + 8] = acc1;
    }
    __syncthreads();   // covers Ws/bs and side visibility

    // -------- GEMM phase: thread = 2 rows (row0, row0+1) x 4 cols (cg) ------
    float4 bb = ((const float4*)bs)[cg];
    float4 h0 = bb, h1 = bb;

    const float* s0 = &side[rr * 2][0];
    const float* s1 = &side[rr * 2 + 1][0];
    #pragma unroll 16
    for (int k = 0; k < 64; k++) {
        float4 w = Ws[k * 16 + cg];
        float a = s0[k], c = s1[k];
        h0.x = fmaf(a, w.x, h0.x); h0.y = fmaf(a, w.y, h0.y);
        h0.z = fmaf(a, w.z, h0.z); h0.w = fmaf(a, w.w, h0.w);
        h1.x = fmaf(c, w.x, h1.x); h1.y = fmaf(c, w.y, h1.y);
        h1.z = fmaf(c, w.z, h1.z); h1.w = fmaf(c, w.w, h1.w);
    }

    // -------- dropout (precomputed) + ego_next + row-norm + out -------------
    #pragma unroll
    for (int m = 0; m < 2; m++) {
        int row = row0 + m;
        float4 hm = (m == 0) ? h0 : h1;
        hm.x = (dmask >> (m * 4 + 0)) & 1u ? hm.x * (1.0f / 0.9f) : 0.0f;
        hm.y = (dmask >> (m * 4 + 1)) & 1u ? hm.y * (1.0f / 0.9f) : 0.0f;
        hm.z = (dmask >> (m * 4 + 2)) & 1u ? hm.z * (1.0f / 0.9f) : 0.0f;
        hm.w = (dmask >> (m * 4 + 3)) & 1u ? hm.w * (1.0f / 0.9f) : 0.0f;

        float ss = hm.x * hm.x + hm.y * hm.y + hm.z * hm.z + hm.w * hm.w;
        // 16 lanes (cg 0..15, same rr) share this row -> xor masks 1,2,4,8
        #pragma unroll
        for (int msk = 1; msk <= 8; msk <<= 1)
            ss += __shfl_xor_sync(0xffffffffu, ss, msk);

        float invn = 1.0f / fmaxf(sqrtf(ss), 1e-12f);

        if (row < n) {
            egoOut[(size_t)row * 16 + cg] = hm;
            float4 o;
            o.x = hm.x * invn; o.y = hm.y * invn;
            o.z = hm.z * invn; o.w = hm.w * invn;
            out4[(size_t)row * 64 + (size_t)(layer + 1) * 16 + cg] = o;
            if (copyEmb)
                out4[(size_t)row * 64 + cg] = embIn[(size_t)row * 16 + cg];
        }
    }
}

// ------------------------------ host entry ---------------------------------
extern "C" void kernel_launch(void* const* d_in, const int* in_sizes, int n_in,
                              void* d_out, int out_size) {
    const int*   rows = (const int*)d_in[0];
    const int*   cols = (const int*)d_in[1];
    const float* vals = (const float*)d_in[2];
    const float* emb  = (const float*)d_in[3];
    const float* W0   = (const float*)d_in[4];
    const float* b0   = (const float*)d_in[5];
    const float* W1   = (const float*)d_in[6];
    const float* b1   = (const float*)d_in[7];
    const float* W2   = (const float*)d_in[8];
    const float* b2   = (const float*)d_in[9];

    int E = in_sizes[0];
    int N = in_sizes[3] / 64;
    if (E > NEDGE_MAX) E = NEDGE_MAX;
    if (N > NROWS_MAX) N = NROWS_MAX;
    float* out = (float*)d_out;

    // subkeys of jax.random.key(42) -> split(.,4): [k_node, k0, k1, k2]
    U2 kn = threefry2x32(0u, 42u, 0u, 0u);
    U2 kA = threefry2x32(0u, 42u, 0u, 1u);
    U2 kB = threefry2x32(0u, 42u, 0u, 2u);
    U2 kC = threefry2x32(0u, 42u, 0u, 3u);

    int tb = 256;
    int nb = (N + 1023) / 1024;
    int hstride = (((E + 3) / 4) + 31) & ~31;
    // launches: [0]hist [1]scan1 [2]scan3 [3]scatter <- ncu
    //           [4]sortfill [5]layer0 [6]layer1 [7]layer2
    k_hist    <<<(hstride + tb - 1) / tb, tb>>>(rows, E, kn.x, kn.y, hstride);
    k_scan1   <<<nb, 1024>>>(N);
    k_scan3   <<<nb, 1024>>>(N, nb);
    k_scatter <<<(E + tb - 1) / tb, tb>>>(rows, E);
    k_sortfill<<<(N + tb - 1) / tb, tb>>>(cols, vals, N);

    int gb = (N + LB_ROWS - 1) / LB_ROWS;
    k_layer<<<gb, LB_THREADS>>>(0, (const float4*)emb, 1, W0, b0,
                                (float4*)out, 0, kA.x, kA.y, 1, N);
    k_layer<<<gb, LB_THREADS>>>(1, (const float4*)emb, 2, W1, b1,
                                (float4*)out, 1, kB.x, kB.y, 0, N);
    k_layer<<<gb, LB_THREADS>>>(2, (const float4*)emb, 1, W2, b2,
                                (float4*)out, 2, kC.x, kC.y, 0, N);
}